// round 8
// baseline (speedup 1.0000x reference)
#include <cuda_runtime.h>
#include <cuda_fp16.h>

// Problem constants (fixed by the dataset)
#define BB 8
#define NXX 512
#define NRR 512
#define DD 256
#define HH 256

// Scratch (no cudaMalloc allowed)
__device__ float g_hX[BB * NXX * HH];       // [b, x, h]
__device__ float g_hR[BB * NRR * HH];       // [b, r, h]
__device__ float g_S[BB * NXX * NRR];       // [b, x, r]
__device__ float g_rowsum[BB * NRR];        // [b, r]  sum_x exp(S)

// ---------------------------------------------------------------------------
// helpers
// ---------------------------------------------------------------------------
__device__ __forceinline__ unsigned f2tf32(float x) {
    unsigned r;
    asm("cvt.rna.tf32.f32 %0, %1;" : "=r"(r) : "f"(x));
    return r;
}

__device__ __forceinline__ void mma_tf32(float* c, const unsigned* a, const unsigned* b) {
    asm volatile(
        "mma.sync.aligned.m16n8k8.row.col.f32.tf32.tf32.f32 "
        "{%0,%1,%2,%3}, {%4,%5,%6,%7}, {%8,%9}, {%0,%1,%2,%3};\n"
        : "+f"(c[0]), "+f"(c[1]), "+f"(c[2]), "+f"(c[3])
        : "r"(a[0]), "r"(a[1]), "r"(a[2]), "r"(a[3]), "r"(b[0]), "r"(b[1]));
}

__device__ __forceinline__ void cp_async16(void* smem, const void* gmem) {
    unsigned s = (unsigned)__cvta_generic_to_shared(smem);
    asm volatile("cp.async.cg.shared.global [%0], [%1], 16;" :: "r"(s), "l"(gmem));
}
__device__ __forceinline__ void cp_commit() {
    asm volatile("cp.async.commit_group;" ::: "memory");
}
__device__ __forceinline__ void cp_wait0() {
    asm volatile("cp.async.wait_group 0;" ::: "memory");
}

// ---------------------------------------------------------------------------
// Kernel 1: projection GEMM (tf32 MMA, double-buffered)
// out[m,h] = sum_d A[m,d] * W[h,d] + bias[h];  z selects (X)->hX vs (ref)->hR
// ---------------------------------------------------------------------------
__global__ __launch_bounds__(256) void proj_mma_kernel(
    const float* __restrict__ A0, const float* __restrict__ W0,
    const float* __restrict__ bias0, float* __restrict__ out0,
    const float* __restrict__ A1, const float* __restrict__ W1,
    const float* __restrict__ bias1, float* __restrict__ out1)
{
    const float* A    = blockIdx.z ? A1 : A0;
    const float* W    = blockIdx.z ? W1 : W0;
    const float* bias = blockIdx.z ? bias1 : bias0;
    float* out        = blockIdx.z ? out1 : out0;

    __shared__ unsigned As[2][128][36];   // [buf][m][k]
    __shared__ unsigned Ws[2][64][36];    // [buf][n][k]

    const int tid  = threadIdx.x;
    const int lane = tid & 31;
    const int warp = tid >> 5;
    const int wm = warp >> 1;
    const int wn = warp & 1;
    const int m0 = blockIdx.x * 128;
    const int n0 = blockIdx.y * 64;

    const int fr = lane >> 2;
    const int fc = lane & 3;

    const int ar = tid >> 1;
    const int aq = (tid & 1) << 4;
    const int wr = tid >> 2;
    const int wq = (tid & 3) << 3;

    float c[2][4][4] = {};

    {
        const float* Arow = &A[(size_t)(m0 + ar) * DD + aq];
        const float* Wrow = &W[(size_t)(n0 + wr) * DD + wq];
#pragma unroll
        for (int u = 0; u < 4; u++) {
            float4 v = *(const float4*)&Arow[4 * u];
            As[0][ar][aq + 4*u + 0] = f2tf32(v.x); As[0][ar][aq + 4*u + 1] = f2tf32(v.y);
            As[0][ar][aq + 4*u + 2] = f2tf32(v.z); As[0][ar][aq + 4*u + 3] = f2tf32(v.w);
        }
#pragma unroll
        for (int u = 0; u < 2; u++) {
            float4 v = *(const float4*)&Wrow[4 * u];
            Ws[0][wr][wq + 4*u + 0] = f2tf32(v.x); Ws[0][wr][wq + 4*u + 1] = f2tf32(v.y);
            Ws[0][wr][wq + 4*u + 2] = f2tf32(v.z); Ws[0][wr][wq + 4*u + 3] = f2tf32(v.w);
        }
    }
    __syncthreads();

    int cur = 0;
    for (int kc = 0; kc < DD; kc += 32) {
        const int nk = kc + 32;
        float4 pa[4], pw[2];
        if (nk < DD) {
            const float* Arow = &A[(size_t)(m0 + ar) * DD + nk + aq];
            const float* Wrow = &W[(size_t)(n0 + wr) * DD + nk + wq];
#pragma unroll
            for (int u = 0; u < 4; u++) pa[u] = *(const float4*)&Arow[4 * u];
#pragma unroll
            for (int u = 0; u < 2; u++) pw[u] = *(const float4*)&Wrow[4 * u];
        }

#pragma unroll
        for (int ks = 0; ks < 4; ks++) {
            const int k = ks << 3;
            unsigned a[2][4], b[4][2];
#pragma unroll
            for (int mt = 0; mt < 2; mt++) {
                int mb = wm * 32 + mt * 16;
                a[mt][0] = As[cur][mb + fr    ][k + fc    ];
                a[mt][1] = As[cur][mb + fr + 8][k + fc    ];
                a[mt][2] = As[cur][mb + fr    ][k + fc + 4];
                a[mt][3] = As[cur][mb + fr + 8][k + fc + 4];
            }
#pragma unroll
            for (int nt = 0; nt < 4; nt++) {
                int nb = wn * 32 + nt * 8;
                b[nt][0] = Ws[cur][nb + fr][k + fc    ];
                b[nt][1] = Ws[cur][nb + fr][k + fc + 4];
            }
#pragma unroll
            for (int mt = 0; mt < 2; mt++)
#pragma unroll
                for (int nt = 0; nt < 4; nt++)
                    mma_tf32(c[mt][nt], a[mt], b[nt]);
        }

        if (nk < DD) {
            const int nxt = cur ^ 1;
#pragma unroll
            for (int u = 0; u < 4; u++) {
                As[nxt][ar][aq + 4*u + 0] = f2tf32(pa[u].x);
                As[nxt][ar][aq + 4*u + 1] = f2tf32(pa[u].y);
                As[nxt][ar][aq + 4*u + 2] = f2tf32(pa[u].z);
                As[nxt][ar][aq + 4*u + 3] = f2tf32(pa[u].w);
            }
#pragma unroll
            for (int u = 0; u < 2; u++) {
                Ws[nxt][wr][wq + 4*u + 0] = f2tf32(pw[u].x);
                Ws[nxt][wr][wq + 4*u + 1] = f2tf32(pw[u].y);
                Ws[nxt][wr][wq + 4*u + 2] = f2tf32(pw[u].z);
                Ws[nxt][wr][wq + 4*u + 3] = f2tf32(pw[u].w);
            }
            __syncthreads();
            cur = nxt;
        }
    }

#pragma unroll
    for (int mt = 0; mt < 2; mt++) {
        int row0 = m0 + wm * 32 + mt * 16 + fr;
#pragma unroll
        for (int nt = 0; nt < 4; nt++) {
            int col = n0 + wn * 32 + nt * 8 + 2 * fc;
            float2 bv = *(const float2*)&bias[col];
            float2 o0 = {c[mt][nt][0] + bv.x, c[mt][nt][1] + bv.y};
            float2 o1 = {c[mt][nt][2] + bv.x, c[mt][nt][3] + bv.y};
            *(float2*)&out[(size_t)row0 * HH + col]       = o0;
            *(float2*)&out[(size_t)(row0 + 8) * HH + col] = o1;
        }
    }
}

// ---------------------------------------------------------------------------
// Kernel 2: scores  S[b,x,r] = sum_h tanh(hX[b,x,h] + hR[b,r,h]) * v[h] + vb
// f32 tanh path — MUFU lane-throughput floor, ~120us.
// ---------------------------------------------------------------------------
__global__ __launch_bounds__(256) void score_kernel(
    const float* __restrict__ hX, const float* __restrict__ hR,
    const float* __restrict__ vw, const float* __restrict__ vb,
    float* __restrict__ S)
{
    __shared__ float hXs[32][128];
    __shared__ float hRt[128][33];
    __shared__ float v_s[HH];

    const int x0 = blockIdx.x * 32, r0 = blockIdx.y * 32, b = blockIdx.z;
    const int tid = threadIdx.x;
    const int lr = tid & 31;
    const int w  = tid >> 5;

    v_s[tid] = vw[tid];

    const float* hXb = hX + (size_t)(b * NXX + x0) * HH;
    const float* hRb = hR + (size_t)(b * NRR + r0) * HH;

    float acc[4] = {0.f, 0.f, 0.f, 0.f};

    for (int hc = 0; hc < 2; hc++) {
        __syncthreads();
        for (int i = tid; i < 32 * 32; i += 256) {
            int row = i >> 5, c4 = (i & 31) << 2;
            *(float4*)&hXs[row][c4] =
                *(const float4*)&hXb[row * HH + hc * 128 + c4];
        }
        for (int i = tid; i < 32 * 32; i += 256) {
            int row = i >> 5, c4 = (i & 31) << 2;
            float4 v = *(const float4*)&hRb[row * HH + hc * 128 + c4];
            hRt[c4 + 0][row] = v.x; hRt[c4 + 1][row] = v.y;
            hRt[c4 + 2][row] = v.z; hRt[c4 + 3][row] = v.w;
        }
        __syncthreads();

        const float* vv = &v_s[hc * 128];
#pragma unroll 4
        for (int h = 0; h < 128; h++) {
            float hr = hRt[h][lr];
            float vh = vv[h];
#pragma unroll
            for (int j = 0; j < 4; j++) {
                float t = hXs[(w << 2) + j][h] + hr;
                float th;
                asm("tanh.approx.f32 %0, %1;" : "=f"(th) : "f"(t));
                acc[j] = fmaf(th, vh, acc[j]);
            }
        }
    }

    const float vbv = vb[0];
#pragma unroll
    for (int j = 0; j < 4; j++) {
        int x = x0 + (w << 2) + j;
        S[((size_t)b * NXX + x) * NRR + r0 + lr] = acc[j] + vbv;
    }
}

// ---------------------------------------------------------------------------
// Kernel 3: rowsum[b,r] = sum_x exp(S[b,x,r])   (no max-sub: |S| <~ 13, safe)
// ---------------------------------------------------------------------------
__global__ __launch_bounds__(256) void rowsum_kernel(
    const float* __restrict__ S, float* __restrict__ rowsum)
{
    const int r0 = blockIdx.x * 32;
    const int b  = blockIdx.y;
    const int tid = threadIdx.x;
    const int tr = tid & 31;
    const int tg = tid >> 5;

    __shared__ float red[8][32];

    const float* Sb = S + (size_t)b * NXX * NRR + r0;

    float s = 0.f;
    for (int x = tg * 64; x < tg * 64 + 64; x++)
        s += __expf(Sb[(size_t)x * NRR + tr]);
    red[tg][tr] = s;
    __syncthreads();
    if (tg == 0) {
        float ss = red[0][tr];
#pragma unroll
        for (int i = 1; i < 8; i++) ss += red[i][tr];
        rowsum[b * NRR + r0 + tr] = ss;
    }
}

// ---------------------------------------------------------------------------
// Kernel 4 (fused): out[b,r,e] = (sum_x exp(S[b,x,r]) * X[b,x,e]) / rowsum[b,r]
// cp.async 2-stage pipeline; S exp'd in-place in smem per chunk.
// Tile 64r x 64e, k-chunk 32. Warps 2(m) x 4(n), warp tile 32m x 16n.
// ---------------------------------------------------------------------------
__global__ __launch_bounds__(256) void outgemm_fused_kernel(
    const float* __restrict__ S, const float* __restrict__ X,
    const float* __restrict__ rowsum, float* __restrict__ out)
{
    __shared__ float Ss[2][32][72];   // [buf][k(x)][r]  raw -> exp'd in place
    __shared__ float Xs[2][32][72];   // [buf][k(x)][e]

    const int tid  = threadIdx.x;
    const int lane = tid & 31;
    const int warp = tid >> 5;
    const int wm = warp >> 2;          // 0..1
    const int wn = warp & 3;           // 0..3
    const int r0 = blockIdx.x * 64;
    const int e0 = blockIdx.y * 64;
    const int b  = blockIdx.z;

    const int fr = lane >> 2;
    const int fc = lane & 3;

    const float* Sb = S + (size_t)b * NXX * NRR;
    const float* Xb = X + (size_t)b * NXX * DD;

    const int lrow = tid >> 3;             // 0..31 (k row)
    const int lq   = (tid & 7) << 3;       // 0..56 (8 floats = 2 x 16B)

    float c[2][2][4] = {};

    // prologue: chunk 0
    cp_async16(&Ss[0][lrow][lq    ], &Sb[(size_t)lrow * NRR + r0 + lq    ]);
    cp_async16(&Ss[0][lrow][lq + 4], &Sb[(size_t)lrow * NRR + r0 + lq + 4]);
    cp_async16(&Xs[0][lrow][lq    ], &Xb[(size_t)lrow * DD  + e0 + lq    ]);
    cp_async16(&Xs[0][lrow][lq + 4], &Xb[(size_t)lrow * DD  + e0 + lq + 4]);
    cp_commit();

    for (int i = 0; i < 16; i++) {
        const int cur = i & 1;
        cp_wait0();
        __syncthreads();

        // issue chunk i+1 into the other buffer (its old contents, chunk i-1,
        // were consumed before this barrier)
        if (i + 1 < 16) {
            const int nxt = cur ^ 1;
            const size_t krow = (size_t)((i + 1) * 32 + lrow);
            cp_async16(&Ss[nxt][lrow][lq    ], &Sb[krow * NRR + r0 + lq    ]);
            cp_async16(&Ss[nxt][lrow][lq + 4], &Sb[krow * NRR + r0 + lq + 4]);
            cp_async16(&Xs[nxt][lrow][lq    ], &Xb[krow * DD  + e0 + lq    ]);
            cp_async16(&Xs[nxt][lrow][lq + 4], &Xb[krow * DD  + e0 + lq + 4]);
            cp_commit();
        }

        // exp-writeback: each thread owns Ss[cur][lrow][lq..lq+7]
        {
            float4 v0 = *(float4*)&Ss[cur][lrow][lq];
            float4 v1 = *(float4*)&Ss[cur][lrow][lq + 4];
            v0.x = __expf(v0.x); v0.y = __expf(v0.y);
            v0.z = __expf(v0.z); v0.w = __expf(v0.w);
            v1.x = __expf(v1.x); v1.y = __expf(v1.y);
            v1.z = __expf(v1.z); v1.w = __expf(v1.w);
            *(float4*)&Ss[cur][lrow][lq]     = v0;
            *(float4*)&Ss[cur][lrow][lq + 4] = v1;
        }
        __syncthreads();

#pragma unroll
        for (int ks = 0; ks < 4; ks++) {
            const int k = ks << 3;
            unsigned a[2][4], bf[2][2];
#pragma unroll
            for (int mt = 0; mt < 2; mt++) {
                int mb = wm * 32 + mt * 16;
                a[mt][0] = f2tf32(Ss[cur][k + fc    ][mb + fr    ]);
                a[mt][1] = f2tf32(Ss[cur][k + fc    ][mb + fr + 8]);
                a[mt][2] = f2tf32(Ss[cur][k + fc + 4][mb + fr    ]);
                a[mt][3] = f2tf32(Ss[cur][k + fc + 4][mb + fr + 8]);
            }
#pragma unroll
            for (int nt = 0; nt < 2; nt++) {
                int nb = wn * 16 + nt * 8;
                bf[nt][0] = f2tf32(Xs[cur][k + fc    ][nb + fr]);
                bf[nt][1] = f2tf32(Xs[cur][k + fc + 4][nb + fr]);
            }
#pragma unroll
            for (int mt = 0; mt < 2; mt++)
#pragma unroll
                for (int nt = 0; nt < 2; nt++)
                    mma_tf32(c[mt][nt], a[mt], bf[nt]);
        }
    }

#pragma unroll
    for (int mt = 0; mt < 2; mt++) {
        int row0 = r0 + wm * 32 + mt * 16 + fr;
        float inv0 = 1.0f / rowsum[b * NRR + row0];
        float inv1 = 1.0f / rowsum[b * NRR + row0 + 8];
#pragma unroll
        for (int nt = 0; nt < 2; nt++) {
            int col = e0 + wn * 16 + nt * 8 + 2 * fc;
            float2 o0 = {c[mt][nt][0] * inv0, c[mt][nt][1] * inv0};
            float2 o1 = {c[mt][nt][2] * inv1, c[mt][nt][3] * inv1};
            *(float2*)&out[((size_t)b * NRR + row0) * DD + col]     = o0;
            *(float2*)&out[((size_t)b * NRR + row0 + 8) * DD + col] = o1;
        }
    }
}

// ---------------------------------------------------------------------------
extern "C" void kernel_launch(void* const* d_in, const int* in_sizes, int n_in,
                              void* d_out, int out_size)
{
    const float* X     = (const float*)d_in[0];
    const float* ref   = (const float*)d_in[1];
    const float* W_X   = (const float*)d_in[2];
    const float* b_X   = (const float*)d_in[3];
    const float* W_ref = (const float*)d_in[4];
    const float* b_ref = (const float*)d_in[5];
    const float* v_w   = (const float*)d_in[6];
    const float* v_b   = (const float*)d_in[7];
    float* out = (float*)d_out;

    float *hX, *hR, *S, *rowsum;
    cudaGetSymbolAddress((void**)&hX,     g_hX);
    cudaGetSymbolAddress((void**)&hR,     g_hR);
    cudaGetSymbolAddress((void**)&S,      g_S);
    cudaGetSymbolAddress((void**)&rowsum, g_rowsum);

    // Projections (tf32 MMA, double-buffered)
    proj_mma_kernel<<<dim3(BB * NXX / 128, HH / 64, 2), 256>>>(
        X, W_X, b_X, hX, ref, W_ref, b_ref, hR);

    // Scores (f32 tanh, MUFU lane-throughput bound)
    score_kernel<<<dim3(NXX / 32, NRR / 32, BB), 256>>>(hX, hR, v_w, v_b, S);

    // Softmax denominator only
    rowsum_kernel<<<dim3(NRR / 32, BB), 256>>>(S, rowsum);

    // Fused exp + weighted sum + normalize (tf32 MMA, cp.async pipeline)
    outgemm_fused_kernel<<<dim3(NRR / 64, DD / 64, BB), 256>>>(S, X, rowsum, out);
}

// round 10
// speedup vs baseline: 1.1384x; 1.1384x over previous
#include <cuda_runtime.h>
#include <cuda_fp16.h>

// Problem constants (fixed by the dataset)
#define BB 8
#define NXX 512
#define NRR 512
#define DD 256
#define HH 256

// Score-kernel hybrid split: HM h-values via MUFU tanh, HP via FFMA2 reciprocal
#define HMU 168
#define HPOLY 88
#define HM_PH 84     // per phase (2 phases)
#define HP_PH 44     // per phase (22 pairs)

// Scratch (no cudaMalloc allowed)
__device__ float g_hX[BB * NXX * HH];       // [b, x, h]
__device__ float g_hR[BB * NRR * HH];       // [b, r, h]
__device__ float g_S[BB * NXX * NRR];       // [b, x, r]
__device__ float g_P[BB * NXX * NRR];       // [b, x, r]  tf32(exp(S))
__device__ float g_rowsum[BB * NRR];        // [b, r]
__device__ float g_Xr[BB * NXX * DD];       // tf32-rounded X
__device__ float g_Rr[BB * NRR * DD];       // tf32-rounded ref
__device__ float g_WXr[HH * DD];            // tf32-rounded W_X
__device__ float g_WRr[HH * DD];            // tf32-rounded W_ref

// ---------------------------------------------------------------------------
// helpers
// ---------------------------------------------------------------------------
__device__ __forceinline__ unsigned f2tf32(float x) {
    unsigned r;
    asm("cvt.rna.tf32.f32 %0, %1;" : "=r"(r) : "f"(x));
    return r;
}

__device__ __forceinline__ void mma_tf32(float* c, const unsigned* a, const unsigned* b) {
    asm volatile(
        "mma.sync.aligned.m16n8k8.row.col.f32.tf32.tf32.f32 "
        "{%0,%1,%2,%3}, {%4,%5,%6,%7}, {%8,%9}, {%0,%1,%2,%3};\n"
        : "+f"(c[0]), "+f"(c[1]), "+f"(c[2]), "+f"(c[3])
        : "r"(a[0]), "r"(a[1]), "r"(a[2]), "r"(a[3]), "r"(b[0]), "r"(b[1]));
}

__device__ __forceinline__ void cp_async16(void* smem, const void* gmem) {
    unsigned s = (unsigned)__cvta_generic_to_shared(smem);
    asm volatile("cp.async.cg.shared.global [%0], [%1], 16;" :: "r"(s), "l"(gmem));
}
__device__ __forceinline__ void cp_commit() {
    asm volatile("cp.async.commit_group;" ::: "memory");
}
__device__ __forceinline__ void cp_wait0() {
    asm volatile("cp.async.wait_group 0;" ::: "memory");
}

// packed f32x2 (Blackwell dual-FP32)
__device__ __forceinline__ void fma2(unsigned long long& d, unsigned long long a,
                                     unsigned long long b, unsigned long long c) {
    asm("fma.rn.f32x2 %0, %1, %2, %3;" : "=l"(d) : "l"(a), "l"(b), "l"(c));
}
__device__ __forceinline__ void mul2(unsigned long long& d, unsigned long long a,
                                     unsigned long long b) {
    asm("mul.rn.f32x2 %0, %1, %2;" : "=l"(d) : "l"(a), "l"(b));
}

// ---------------------------------------------------------------------------
// Kernel 0: pre-round inputs to canonical tf32 (low 13 mantissa bits zero)
// y=0: X -> Xr, y=1: ref -> Rr, y=2: W_X -> WXr, y=3: W_ref -> WRr
// ---------------------------------------------------------------------------
__global__ __launch_bounds__(256) void prep_round_kernel(
    const float* __restrict__ X, const float* __restrict__ ref,
    const float* __restrict__ WX, const float* __restrict__ WR,
    float* __restrict__ Xr, float* __restrict__ Rr,
    float* __restrict__ WXr, float* __restrict__ WRr)
{
    const float* src; float* dst; int n4;
    switch (blockIdx.y) {
        case 0: src = X;  dst = Xr;  n4 = BB * NXX * DD / 4; break;
        case 1: src = ref; dst = Rr; n4 = BB * NRR * DD / 4; break;
        case 2: src = WX; dst = WXr; n4 = HH * DD / 4; break;
        default: src = WR; dst = WRr; n4 = HH * DD / 4; break;
    }
    for (int i = blockIdx.x * 256 + threadIdx.x; i < n4; i += gridDim.x * 256) {
        float4 v = *(const float4*)&src[4 * i];
        v.x = __uint_as_float(f2tf32(v.x));
        v.y = __uint_as_float(f2tf32(v.y));
        v.z = __uint_as_float(f2tf32(v.z));
        v.w = __uint_as_float(f2tf32(v.w));
        *(float4*)&dst[4 * i] = v;
    }
}

// ---------------------------------------------------------------------------
// Kernel 1: projection GEMM (tf32 MMA, double-buffered; inputs pre-rounded,
// so NO cvt anywhere in the loop — raw float4 STS, reinterpret at frag load)
// ---------------------------------------------------------------------------
__global__ __launch_bounds__(256) void proj_mma_kernel(
    const float* __restrict__ A0, const float* __restrict__ W0,
    const float* __restrict__ bias0, float* __restrict__ out0,
    const float* __restrict__ A1, const float* __restrict__ W1,
    const float* __restrict__ bias1, float* __restrict__ out1)
{
    const float* A    = blockIdx.z ? A1 : A0;
    const float* W    = blockIdx.z ? W1 : W0;
    const float* bias = blockIdx.z ? bias1 : bias0;
    float* out        = blockIdx.z ? out1 : out0;

    __shared__ float As[2][128][36];
    __shared__ float Ws[2][64][36];

    const int tid  = threadIdx.x;
    const int lane = tid & 31;
    const int warp = tid >> 5;
    const int wm = warp >> 1;
    const int wn = warp & 1;
    const int m0 = blockIdx.x * 128;
    const int n0 = blockIdx.y * 64;

    const int fr = lane >> 2;
    const int fc = lane & 3;

    const int ar = tid >> 1;
    const int aq = (tid & 1) << 4;
    const int wr = tid >> 2;
    const int wq = (tid & 3) << 3;

    float c[2][4][4] = {};

    {
        const float* Arow = &A[(size_t)(m0 + ar) * DD + aq];
        const float* Wrow = &W[(size_t)(n0 + wr) * DD + wq];
#pragma unroll
        for (int u = 0; u < 4; u++)
            *(float4*)&As[0][ar][aq + 4*u] = *(const float4*)&Arow[4*u];
#pragma unroll
        for (int u = 0; u < 2; u++)
            *(float4*)&Ws[0][wr][wq + 4*u] = *(const float4*)&Wrow[4*u];
    }
    __syncthreads();

    int cur = 0;
    for (int kc = 0; kc < DD; kc += 32) {
        const int nk = kc + 32;
        float4 pa[4], pw[2];
        if (nk < DD) {
            const float* Arow = &A[(size_t)(m0 + ar) * DD + nk + aq];
            const float* Wrow = &W[(size_t)(n0 + wr) * DD + nk + wq];
#pragma unroll
            for (int u = 0; u < 4; u++) pa[u] = *(const float4*)&Arow[4*u];
#pragma unroll
            for (int u = 0; u < 2; u++) pw[u] = *(const float4*)&Wrow[4*u];
        }

#pragma unroll
        for (int ks = 0; ks < 4; ks++) {
            const int k = ks << 3;
            unsigned a[2][4], b[4][2];
#pragma unroll
            for (int mt = 0; mt < 2; mt++) {
                int mb = wm * 32 + mt * 16;
                a[mt][0] = __float_as_uint(As[cur][mb + fr    ][k + fc    ]);
                a[mt][1] = __float_as_uint(As[cur][mb + fr + 8][k + fc    ]);
                a[mt][2] = __float_as_uint(As[cur][mb + fr    ][k + fc + 4]);
                a[mt][3] = __float_as_uint(As[cur][mb + fr + 8][k + fc + 4]);
            }
#pragma unroll
            for (int nt = 0; nt < 4; nt++) {
                int nb = wn * 32 + nt * 8;
                b[nt][0] = __float_as_uint(Ws[cur][nb + fr][k + fc    ]);
                b[nt][1] = __float_as_uint(Ws[cur][nb + fr][k + fc + 4]);
            }
#pragma unroll
            for (int mt = 0; mt < 2; mt++)
#pragma unroll
                for (int nt = 0; nt < 4; nt++)
                    mma_tf32(c[mt][nt], a[mt], b[nt]);
        }

        if (nk < DD) {
            const int nxt = cur ^ 1;
#pragma unroll
            for (int u = 0; u < 4; u++) *(float4*)&As[nxt][ar][aq + 4*u] = pa[u];
#pragma unroll
            for (int u = 0; u < 2; u++) *(float4*)&Ws[nxt][wr][wq + 4*u] = pw[u];
            __syncthreads();
            cur = nxt;
        }
    }

#pragma unroll
    for (int mt = 0; mt < 2; mt++) {
        int row0 = m0 + wm * 32 + mt * 16 + fr;
#pragma unroll
        for (int nt = 0; nt < 4; nt++) {
            int col = n0 + wn * 32 + nt * 8 + 2 * fc;
            float2 bv = *(const float2*)&bias[col];
            float2 o0 = {c[mt][nt][0] + bv.x, c[mt][nt][1] + bv.y};
            float2 o1 = {c[mt][nt][2] + bv.x, c[mt][nt][3] + bv.y};
            *(float2*)&out[(size_t)row0 * HH + col]       = o0;
            *(float2*)&out[(size_t)(row0 + 8) * HH + col] = o1;
        }
    }
}

// ---------------------------------------------------------------------------
// Score: hybrid.  h < HMU: MUFU tanh.  h >= HMU: tanh(t)=1-2/(1+e^{2t}) with
// e^{2t}=e^{2hX}*e^{2hR} precomputed at tile load; reciprocal on FMA pipe via
// bit-trick seed (negated: 0xFEF127EA-bits) + 2 Newton steps, packed f32x2.
// score = sum_MUFU v*tanh + sum_poly v + sum_poly (2v)*gneg, gneg -> -1/(1+p)
// ---------------------------------------------------------------------------
__device__ __forceinline__ void poly_pair(
    const float2 (&pXs2)[32][22], const float2 (&pRt2)[22][33],
    const float2* v2p, int q, int w4, int lr, unsigned long long accp[4])
{
    unsigned long long pR2 = *(const unsigned long long*)&pRt2[q][lr];
    unsigned long long vv2 = *(const unsigned long long*)&v2p[q];
#pragma unroll
    for (int j = 0; j < 4; j++) {
        unsigned long long pX2 = *(const unsigned long long*)&pXs2[w4 + j][q];
        unsigned long long d2, t2, g2;
        unsigned lo, hi;
        fma2(d2, pX2, pR2, 0x3F8000003F800000ULL);            // d = p + 1
        asm("mov.b64 {%0,%1}, %2;" : "=r"(lo), "=r"(hi) : "l"(d2));
        lo = 0xFEF127EAu - lo;                                 // -1/d seed
        hi = 0xFEF127EAu - hi;
        asm("mov.b64 %0, {%1,%2};" : "=l"(g2) : "r"(lo), "r"(hi));
        fma2(t2, d2, g2, 0x4000000040000000ULL);               // t = 2 - d*g
        mul2(g2, g2, t2);
        fma2(t2, d2, g2, 0x4000000040000000ULL);
        mul2(g2, g2, t2);                                      // gneg ~ -1/d
        fma2(accp[j], vv2, g2, accp[j]);                       // += 2v * gneg
    }
}

__global__ __launch_bounds__(256) void score_kernel(
    const float* __restrict__ hX, const float* __restrict__ hR,
    const float* __restrict__ vw, const float* __restrict__ vb,
    float* __restrict__ S)
{
    __shared__ float  hXs[32][HM_PH];     // [x][h] MUFU range (row-major bcast)
    __shared__ float  hRtM[HM_PH][33];    // [h][r] transposed
    __shared__ float2 pXs2[32][22];       // e^{2hX} pairs, poly range
    __shared__ float2 pRt2[22][33];       // e^{2hR} pairs transposed
    __shared__ float  v_s[HH];
    __shared__ float2 v2s[44];            // (2v, 2v) for poly range

    const int x0 = blockIdx.x * 32, r0 = blockIdx.y * 32, b = blockIdx.z;
    const int tid = threadIdx.x;
    const int lr = tid & 31;
    const int w  = tid >> 5;
    const int w4 = w << 2;

    v_s[tid] = vw[tid];
    if (tid < 44) {
        float a = vw[HMU + 2 * tid], c = vw[HMU + 2 * tid + 1];
        v2s[tid] = make_float2(2.0f * a, 2.0f * c);
    }

    const float* hXb = hX + (size_t)(b * NXX + x0) * HH;
    const float* hRb = hR + (size_t)(b * NRR + r0) * HH;

    float acc[4] = {0.f, 0.f, 0.f, 0.f};
    unsigned long long accp[4] = {0ULL, 0ULL, 0ULL, 0ULL};

    for (int ph = 0; ph < 2; ph++) {
        __syncthreads();
        // MUFU-range tiles: 32 rows x 21 float4
        for (int i = tid; i < 32 * 21; i += 256) {
            int row = i / 21, q = (i % 21) * 4;
            float4 vx = *(const float4*)&hXb[row * HH + ph * HM_PH + q];
            *(float4*)&hXs[row][q] = vx;
            float4 vr = *(const float4*)&hRb[row * HH + ph * HM_PH + q];
            hRtM[q + 0][row] = vr.x; hRtM[q + 1][row] = vr.y;
            hRtM[q + 2][row] = vr.z; hRtM[q + 3][row] = vr.w;
        }
        // poly-range tiles (exponentiate at load): 32 rows x 11 float4
        for (int i = tid; i < 32 * 11; i += 256) {
            int row = i / 11, q = (i % 11) * 4;
            float4 vx = *(const float4*)&hXb[row * HH + HMU + ph * HP_PH + q];
            pXs2[row][(q >> 1)    ] = make_float2(__expf(2.f * vx.x), __expf(2.f * vx.y));
            pXs2[row][(q >> 1) + 1] = make_float2(__expf(2.f * vx.z), __expf(2.f * vx.w));
            float4 vr = *(const float4*)&hRb[row * HH + HMU + ph * HP_PH + q];
            pRt2[(q >> 1)    ][row] = make_float2(__expf(2.f * vr.x), __expf(2.f * vr.y));
            pRt2[(q >> 1) + 1][row] = make_float2(__expf(2.f * vr.z), __expf(2.f * vr.w));
        }
        __syncthreads();

        const float* vv = &v_s[ph * HM_PH];
        const float2* v2p = &v2s[ph * 22];

        for (int it = 0; it < 21; it++) {
#pragma unroll
            for (int hh = 0; hh < 4; hh++) {
                const int h = it * 4 + hh;
                float hr = hRtM[h][lr];
                float vh = vv[h];
#pragma unroll
                for (int j = 0; j < 4; j++) {
                    float t = hXs[w4 + j][h] + hr;
                    float th;
                    asm("tanh.approx.f32 %0, %1;" : "=f"(th) : "f"(t));
                    acc[j] = fmaf(th, vh, acc[j]);
                }
            }
            poly_pair(pXs2, pRt2, v2p, it, w4, lr, accp);
        }
        poly_pair(pXs2, pRt2, v2p, 21, w4, lr, accp);
    }

    // constant term: vb + sum of v over poly range
    float C = vb[0];
#pragma unroll 8
    for (int h = HMU; h < HH; h++) C += v_s[h];

#pragma unroll
    for (int j = 0; j < 4; j++) {
        unsigned lo, hi;
        asm("mov.b64 {%0,%1}, %2;" : "=r"(lo), "=r"(hi) : "l"(accp[j]));
        float pj = __uint_as_float(lo) + __uint_as_float(hi);
        int x = x0 + w4 + j;
        S[((size_t)b * NXX + x) * NRR + r0 + lr] = acc[j] + pj + C;
    }
}

// ---------------------------------------------------------------------------
// Kernel 3: P = tf32(exp(S)), rowsum[b,r] = sum_x exp(S)  (|S| <~ 13, safe)
// ---------------------------------------------------------------------------
__global__ __launch_bounds__(256) void rowsumP_kernel(
    const float* __restrict__ S, float* __restrict__ P,
    float* __restrict__ rowsum)
{
    const int r0 = blockIdx.x * 32;
    const int b  = blockIdx.y;
    const int tid = threadIdx.x;
    const int tr = tid & 31;
    const int tg = tid >> 5;

    __shared__ float red[8][32];

    const float* Sb = S + (size_t)b * NXX * NRR + r0;
    float* Pb = P + (size_t)b * NXX * NRR + r0;

    float s = 0.f;
    for (int x = tg * 64; x < tg * 64 + 64; x++) {
        float e = __expf(Sb[(size_t)x * NRR + tr]);
        s += e;
        Pb[(size_t)x * NRR + tr] = __uint_as_float(f2tf32(e));
    }
    red[tg][tr] = s;
    __syncthreads();
    if (tg == 0) {
        float ss = red[0][tr];
#pragma unroll
        for (int i = 1; i < 8; i++) ss += red[i][tr];
        rowsum[b * NRR + r0 + tr] = ss;
    }
}

// ---------------------------------------------------------------------------
// Kernel 4: out[b,r,e] = (sum_x P[b,x,r] * Xr[b,x,e]) / rowsum[b,r]
// cp.async 2-stage pipeline; operands pre-rounded tf32 -> ZERO cvt in loop.
// Tile 64r x 64e, k-chunk 32.
// ---------------------------------------------------------------------------
__global__ __launch_bounds__(256) void outgemm_kernel(
    const float* __restrict__ P, const float* __restrict__ X,
    const float* __restrict__ rowsum, float* __restrict__ out)
{
    __shared__ float Ps[2][32][72];
    __shared__ float Xs[2][32][72];

    const int tid  = threadIdx.x;
    const int lane = tid & 31;
    const int warp = tid >> 5;
    const int wm = warp >> 2;
    const int wn = warp & 3;
    const int r0 = blockIdx.x * 64;
    const int e0 = blockIdx.y * 64;
    const int b  = blockIdx.z;

    const int fr = lane >> 2;
    const int fc = lane & 3;

    const float* Pb = P + (size_t)b * NXX * NRR;
    const float* Xb = X + (size_t)b * NXX * DD;

    const int lrow = tid >> 3;
    const int lq   = (tid & 7) << 3;

    float c[2][2][4] = {};

    cp_async16(&Ps[0][lrow][lq    ], &Pb[(size_t)lrow * NRR + r0 + lq    ]);
    cp_async16(&Ps[0][lrow][lq + 4], &Pb[(size_t)lrow * NRR + r0 + lq + 4]);
    cp_async16(&Xs[0][lrow][lq    ], &Xb[(size_t)lrow * DD  + e0 + lq    ]);
    cp_async16(&Xs[0][lrow][lq + 4], &Xb[(size_t)lrow * DD  + e0 + lq + 4]);
    cp_commit();

    for (int i = 0; i < 16; i++) {
        const int cur = i & 1;
        cp_wait0();
        __syncthreads();

        if (i + 1 < 16) {
            const int nxt = cur ^ 1;
            const size_t krow = (size_t)((i + 1) * 32 + lrow);
            cp_async16(&Ps[nxt][lrow][lq    ], &Pb[krow * NRR + r0 + lq    ]);
            cp_async16(&Ps[nxt][lrow][lq + 4], &Pb[krow * NRR + r0 + lq + 4]);
            cp_async16(&Xs[nxt][lrow][lq    ], &Xb[krow * DD  + e0 + lq    ]);
            cp_async16(&Xs[nxt][lrow][lq + 4], &Xb[krow * DD  + e0 + lq + 4]);
            cp_commit();
        }

#pragma unroll
        for (int ks = 0; ks < 4; ks++) {
            const int k = ks << 3;
            unsigned a[2][4], bf[2][2];
#pragma unroll
            for (int mt = 0; mt < 2; mt++) {
                int mb = wm * 32 + mt * 16;
                a[mt][0] = __float_as_uint(Ps[cur][k + fc    ][mb + fr    ]);
                a[mt][1] = __float_as_uint(Ps[cur][k + fc    ][mb + fr + 8]);
                a[mt][2] = __float_as_uint(Ps[cur][k + fc + 4][mb + fr    ]);
                a[mt][3] = __float_as_uint(Ps[cur][k + fc + 4][mb + fr + 8]);
            }
#pragma unroll
            for (int nt = 0; nt < 2; nt++) {
                int nb = wn * 16 + nt * 8;
                bf[nt][0] = __float_as_uint(Xs[cur][k + fc    ][nb + fr]);
                bf[nt][1] = __float_as_uint(Xs[cur][k + fc + 4][nb + fr]);
            }
#pragma unroll
            for (int mt = 0; mt < 2; mt++)
#pragma unroll
                for (int nt = 0; nt < 2; nt++)
                    mma_tf32(c[mt][nt], a[mt], bf[nt]);
        }
    }

#pragma unroll
    for (int mt = 0; mt < 2; mt++) {
        int row0 = r0 + wm * 32 + mt * 16 + fr;
        float inv0 = 1.0f / rowsum[b * NRR + row0];
        float inv1 = 1.0f / rowsum[b * NRR + row0 + 8];
#pragma unroll
        for (int nt = 0; nt < 2; nt++) {
            int col = e0 + wn * 16 + nt * 8 + 2 * fc;
            float2 o0 = {c[mt][nt][0] * inv0, c[mt][nt][1] * inv0};
            float2 o1 = {c[mt][nt][2] * inv1, c[mt][nt][3] * inv1};
            *(float2*)&out[((size_t)b * NRR + row0) * DD + col]     = o0;
            *(float2*)&out[((size_t)b * NRR + row0 + 8) * DD + col] = o1;
        }
    }
}

// ---------------------------------------------------------------------------
extern "C" void kernel_launch(void* const* d_in, const int* in_sizes, int n_in,
                              void* d_out, int out_size)
{
    const float* X     = (const float*)d_in[0];
    const float* ref   = (const float*)d_in[1];
    const float* W_X   = (const float*)d_in[2];
    const float* b_X   = (const float*)d_in[3];
    const float* W_ref = (const float*)d_in[4];
    const float* b_ref = (const float*)d_in[5];
    const float* v_w   = (const float*)d_in[6];
    const float* v_b   = (const float*)d_in[7];
    float* out = (float*)d_out;

    float *hX, *hR, *S, *P, *rowsum, *Xr, *Rr, *WXr, *WRr;
    cudaGetSymbolAddress((void**)&hX,     g_hX);
    cudaGetSymbolAddress((void**)&hR,     g_hR);
    cudaGetSymbolAddress((void**)&S,      g_S);
    cudaGetSymbolAddress((void**)&P,      g_P);
    cudaGetSymbolAddress((void**)&rowsum, g_rowsum);
    cudaGetSymbolAddress((void**)&Xr,     g_Xr);
    cudaGetSymbolAddress((void**)&Rr,     g_Rr);
    cudaGetSymbolAddress((void**)&WXr,    g_WXr);
    cudaGetSymbolAddress((void**)&WRr,    g_WRr);

    // Pre-round operands to canonical tf32
    prep_round_kernel<<<dim3(512, 4), 256>>>(X, ref, W_X, W_ref, Xr, Rr, WXr, WRr);

    // Projections (tf32 MMA, no in-loop cvt)
    proj_mma_kernel<<<dim3(BB * NXX / 128, HH / 64, 2), 256>>>(
        Xr, WXr, b_X, hX, Rr, WRr, b_ref, hR);

    // Scores (MUFU tanh + FFMA2 reciprocal hybrid)
    score_kernel<<<dim3(NXX / 32, NRR / 32, BB), 256>>>(hX, hR, v_w, v_b, S);

    // P = tf32(exp(S)) + softmax denominator
    rowsumP_kernel<<<dim3(NRR / 32, BB), 256>>>(S, P, rowsum);

    // Weighted sum + normalize (tf32 MMA, cp.async, no cvt)
    outgemm_kernel<<<dim3(NRR / 64, DD / 64, BB), 256>>>(P, Xr, rowsum, out);
}

// round 11
// speedup vs baseline: 1.1540x; 1.0138x over previous
#include <cuda_runtime.h>
#include <cuda_fp16.h>

// Problem constants (fixed by the dataset)
#define BB 8
#define NXX 512
#define NRR 512
#define DD 256
#define HH 256

// Score-kernel hybrid split: HMU h-values via MUFU tanh, HPOLY via FFMA2 recip
#define HMU 160
#define HPOLY 96
#define HM_PH 80     // per phase (2 phases)
#define HP_PH 48     // per phase (24 pairs)

// Scratch (no cudaMalloc allowed)
__device__ float g_hX[BB * NXX * HH];       // [b, x, h]
__device__ float g_hR[BB * NRR * HH];       // [b, r, h]
__device__ float g_P[BB * NXX * NRR];       // [b, x, r]  tf32(exp(S))
__device__ float g_psum[BB * 16 * NRR];     // [b, xblk, r] partial exp-sums
__device__ float g_rowsum[BB * NRR];        // [b, r]

// ---------------------------------------------------------------------------
// helpers
// ---------------------------------------------------------------------------
__device__ __forceinline__ unsigned f2tf32(float x) {
    unsigned r;
    asm("cvt.rna.tf32.f32 %0, %1;" : "=r"(r) : "f"(x));
    return r;
}

__device__ __forceinline__ void mma_tf32(float* c, const unsigned* a, const unsigned* b) {
    asm volatile(
        "mma.sync.aligned.m16n8k8.row.col.f32.tf32.tf32.f32 "
        "{%0,%1,%2,%3}, {%4,%5,%6,%7}, {%8,%9}, {%0,%1,%2,%3};\n"
        : "+f"(c[0]), "+f"(c[1]), "+f"(c[2]), "+f"(c[3])
        : "r"(a[0]), "r"(a[1]), "r"(a[2]), "r"(a[3]), "r"(b[0]), "r"(b[1]));
}

__device__ __forceinline__ void cp_async16(void* smem, const void* gmem) {
    unsigned s = (unsigned)__cvta_generic_to_shared(smem);
    asm volatile("cp.async.cg.shared.global [%0], [%1], 16;" :: "r"(s), "l"(gmem));
}
__device__ __forceinline__ void cp_commit() {
    asm volatile("cp.async.commit_group;" ::: "memory");
}
__device__ __forceinline__ void cp_wait0() {
    asm volatile("cp.async.wait_group 0;" ::: "memory");
}

// packed f32x2 (Blackwell dual-FP32)
__device__ __forceinline__ void fma2(unsigned long long& d, unsigned long long a,
                                     unsigned long long b, unsigned long long c) {
    asm("fma.rn.f32x2 %0, %1, %2, %3;" : "=l"(d) : "l"(a), "l"(b), "l"(c));
}
__device__ __forceinline__ void mul2(unsigned long long& d, unsigned long long a,
                                     unsigned long long b) {
    asm("mul.rn.f32x2 %0, %1, %2;" : "=l"(d) : "l"(a), "l"(b));
}

// ---------------------------------------------------------------------------
// Kernel 1: projection GEMM (tf32 MMA, double-buffered). Raw fp32 fed to MMA
// (tf32 reads high 19 bits -> truncation; no cvt anywhere).
// ---------------------------------------------------------------------------
__global__ __launch_bounds__(256) void proj_mma_kernel(
    const float* __restrict__ A0, const float* __restrict__ W0,
    const float* __restrict__ bias0, float* __restrict__ out0,
    const float* __restrict__ A1, const float* __restrict__ W1,
    const float* __restrict__ bias1, float* __restrict__ out1)
{
    const float* A    = blockIdx.z ? A1 : A0;
    const float* W    = blockIdx.z ? W1 : W0;
    const float* bias = blockIdx.z ? bias1 : bias0;
    float* out        = blockIdx.z ? out1 : out0;

    __shared__ float As[2][128][36];
    __shared__ float Ws[2][64][36];

    const int tid  = threadIdx.x;
    const int lane = tid & 31;
    const int warp = tid >> 5;
    const int wm = warp >> 1;
    const int wn = warp & 1;
    const int m0 = blockIdx.x * 128;
    const int n0 = blockIdx.y * 64;

    const int fr = lane >> 2;
    const int fc = lane & 3;

    const int ar = tid >> 1;
    const int aq = (tid & 1) << 4;
    const int wr = tid >> 2;
    const int wq = (tid & 3) << 3;

    float c[2][4][4] = {};

    {
        const float* Arow = &A[(size_t)(m0 + ar) * DD + aq];
        const float* Wrow = &W[(size_t)(n0 + wr) * DD + wq];
#pragma unroll
        for (int u = 0; u < 4; u++)
            *(float4*)&As[0][ar][aq + 4*u] = *(const float4*)&Arow[4*u];
#pragma unroll
        for (int u = 0; u < 2; u++)
            *(float4*)&Ws[0][wr][wq + 4*u] = *(const float4*)&Wrow[4*u];
    }
    __syncthreads();

    int cur = 0;
    for (int kc = 0; kc < DD; kc += 32) {
        const int nk = kc + 32;
        float4 pa[4], pw[2];
        if (nk < DD) {
            const float* Arow = &A[(size_t)(m0 + ar) * DD + nk + aq];
            const float* Wrow = &W[(size_t)(n0 + wr) * DD + nk + wq];
#pragma unroll
            for (int u = 0; u < 4; u++) pa[u] = *(const float4*)&Arow[4*u];
#pragma unroll
            for (int u = 0; u < 2; u++) pw[u] = *(const float4*)&Wrow[4*u];
        }

#pragma unroll
        for (int ks = 0; ks < 4; ks++) {
            const int k = ks << 3;
            unsigned a[2][4], b[4][2];
#pragma unroll
            for (int mt = 0; mt < 2; mt++) {
                int mb = wm * 32 + mt * 16;
                a[mt][0] = __float_as_uint(As[cur][mb + fr    ][k + fc    ]);
                a[mt][1] = __float_as_uint(As[cur][mb + fr + 8][k + fc    ]);
                a[mt][2] = __float_as_uint(As[cur][mb + fr    ][k + fc + 4]);
                a[mt][3] = __float_as_uint(As[cur][mb + fr + 8][k + fc + 4]);
            }
#pragma unroll
            for (int nt = 0; nt < 4; nt++) {
                int nb = wn * 32 + nt * 8;
                b[nt][0] = __float_as_uint(Ws[cur][nb + fr][k + fc    ]);
                b[nt][1] = __float_as_uint(Ws[cur][nb + fr][k + fc + 4]);
            }
#pragma unroll
            for (int mt = 0; mt < 2; mt++)
#pragma unroll
                for (int nt = 0; nt < 4; nt++)
                    mma_tf32(c[mt][nt], a[mt], b[nt]);
        }

        if (nk < DD) {
            const int nxt = cur ^ 1;
#pragma unroll
            for (int u = 0; u < 4; u++) *(float4*)&As[nxt][ar][aq + 4*u] = pa[u];
#pragma unroll
            for (int u = 0; u < 2; u++) *(float4*)&Ws[nxt][wr][wq + 4*u] = pw[u];
            __syncthreads();
            cur = nxt;
        }
    }

#pragma unroll
    for (int mt = 0; mt < 2; mt++) {
        int row0 = m0 + wm * 32 + mt * 16 + fr;
#pragma unroll
        for (int nt = 0; nt < 4; nt++) {
            int col = n0 + wn * 32 + nt * 8 + 2 * fc;
            float2 bv = *(const float2*)&bias[col];
            float2 o0 = {c[mt][nt][0] + bv.x, c[mt][nt][1] + bv.y};
            float2 o1 = {c[mt][nt][2] + bv.x, c[mt][nt][3] + bv.y};
            *(float2*)&out[(size_t)row0 * HH + col]       = o0;
            *(float2*)&out[(size_t)(row0 + 8) * HH + col] = o1;
        }
    }
}

// ---------------------------------------------------------------------------
// Score (fused exp + partial rowsum).  h < HMU: MUFU tanh.  h >= HMU:
// tanh(t)=1-2/(1+e^{2t}), e^{2t}=e^{2hX}*e^{2hR} precomputed at tile load;
// reciprocal on FMA pipe (bit-seed 0xFEF127EA-bits for -1/d, 2 Newton, f32x2).
// Epilogue: P = tf32(exp(score)); per-block partial sums -> psum.
// ---------------------------------------------------------------------------
__device__ __forceinline__ void poly_pair(
    const float2 (&pXs2)[32][24], const float2 (&pRt2)[24][33],
    const float2* v2p, int q, int w4, int lr, unsigned long long accp[4])
{
    unsigned long long pR2 = *(const unsigned long long*)&pRt2[q][lr];
    unsigned long long vv2 = *(const unsigned long long*)&v2p[q];
#pragma unroll
    for (int j = 0; j < 4; j++) {
        unsigned long long pX2 = *(const unsigned long long*)&pXs2[w4 + j][q];
        unsigned long long d2, t2, g2;
        unsigned lo, hi;
        fma2(d2, pX2, pR2, 0x3F8000003F800000ULL);            // d = p + 1
        asm("mov.b64 {%0,%1}, %2;" : "=r"(lo), "=r"(hi) : "l"(d2));
        lo = 0xFEF127EAu - lo;                                 // -1/d seed
        hi = 0xFEF127EAu - hi;
        asm("mov.b64 %0, {%1,%2};" : "=l"(g2) : "r"(lo), "r"(hi));
        fma2(t2, d2, g2, 0x4000000040000000ULL);               // t = 2 - d*g
        mul2(g2, g2, t2);
        fma2(t2, d2, g2, 0x4000000040000000ULL);
        mul2(g2, g2, t2);                                      // gneg ~ -1/d
        fma2(accp[j], vv2, g2, accp[j]);                       // += 2v * gneg
    }
}

__global__ __launch_bounds__(256) void score_kernel(
    const float* __restrict__ hX, const float* __restrict__ hR,
    const float* __restrict__ vw, const float* __restrict__ vb,
    float* __restrict__ P, float* __restrict__ psum)
{
    __shared__ float  hXs[32][HM_PH];     // [x][h] MUFU range
    __shared__ float  hRtM[HM_PH][33];    // [h][r] transposed
    __shared__ float2 pXs2[32][24];       // e^{2hX} pairs, poly range
    __shared__ float2 pRt2[24][33];       // e^{2hR} pairs transposed
    __shared__ float  v_s[HH];
    __shared__ float2 v2s[48];            // (2v, 2v) for poly range
    __shared__ float  red[8][32];

    const int xt = blockIdx.x, rt = blockIdx.y, b = blockIdx.z;
    const int x0 = xt * 32, r0 = rt * 32;
    const int tid = threadIdx.x;
    const int lr = tid & 31;
    const int w  = tid >> 5;
    const int w4 = w << 2;

    v_s[tid] = vw[tid];
    if (tid < 48) {
        float a = vw[HMU + 2 * tid], c = vw[HMU + 2 * tid + 1];
        v2s[tid] = make_float2(2.0f * a, 2.0f * c);
    }

    const float* hXb = hX + (size_t)(b * NXX + x0) * HH;
    const float* hRb = hR + (size_t)(b * NRR + r0) * HH;

    float acc[4] = {0.f, 0.f, 0.f, 0.f};
    unsigned long long accp[4] = {0ULL, 0ULL, 0ULL, 0ULL};

    for (int ph = 0; ph < 2; ph++) {
        __syncthreads();
        // MUFU-range tiles: 32 rows x 20 float4
        for (int i = tid; i < 32 * 20; i += 256) {
            int row = i / 20, q = (i % 20) * 4;
            float4 vx = *(const float4*)&hXb[row * HH + ph * HM_PH + q];
            *(float4*)&hXs[row][q] = vx;
            float4 vr = *(const float4*)&hRb[row * HH + ph * HM_PH + q];
            hRtM[q + 0][row] = vr.x; hRtM[q + 1][row] = vr.y;
            hRtM[q + 2][row] = vr.z; hRtM[q + 3][row] = vr.w;
        }
        // poly-range tiles (exponentiate at load): 32 rows x 12 float4
        for (int i = tid; i < 32 * 12; i += 256) {
            int row = i / 12, q = (i % 12) * 4;
            float4 vx = *(const float4*)&hXb[row * HH + HMU + ph * HP_PH + q];
            pXs2[row][(q >> 1)    ] = make_float2(__expf(2.f * vx.x), __expf(2.f * vx.y));
            pXs2[row][(q >> 1) + 1] = make_float2(__expf(2.f * vx.z), __expf(2.f * vx.w));
            float4 vr = *(const float4*)&hRb[row * HH + HMU + ph * HP_PH + q];
            pRt2[(q >> 1)    ][row] = make_float2(__expf(2.f * vr.x), __expf(2.f * vr.y));
            pRt2[(q >> 1) + 1][row] = make_float2(__expf(2.f * vr.z), __expf(2.f * vr.w));
        }
        __syncthreads();

        const float* vv = &v_s[ph * HM_PH];
        const float2* v2p = &v2s[ph * 24];

        for (int it = 0; it < 20; it++) {
#pragma unroll
            for (int hh = 0; hh < 4; hh++) {
                const int h = it * 4 + hh;
                float hr = hRtM[h][lr];
                float vh = vv[h];
#pragma unroll
                for (int j = 0; j < 4; j++) {
                    float t = hXs[w4 + j][h] + hr;
                    float th;
                    asm("tanh.approx.f32 %0, %1;" : "=f"(th) : "f"(t));
                    acc[j] = fmaf(th, vh, acc[j]);
                }
            }
            poly_pair(pXs2, pRt2, v2p, it, w4, lr, accp);
            if (it >= 16)
                poly_pair(pXs2, pRt2, v2p, 20 + (it - 16), w4, lr, accp);
        }
    }

    // constant term: vb + sum of v over poly range
    float C = vb[0];
#pragma unroll 8
    for (int h = HMU; h < HH; h++) C += v_s[h];

    // epilogue: exp, write tf32(exp), accumulate partial rowsum
    float pt = 0.f;
#pragma unroll
    for (int j = 0; j < 4; j++) {
        unsigned lo, hi;
        asm("mov.b64 {%0,%1}, %2;" : "=r"(lo), "=r"(hi) : "l"(accp[j]));
        float s = acc[j] + __uint_as_float(lo) + __uint_as_float(hi) + C;
        float e = __expf(s);
        pt += e;
        int x = x0 + w4 + j;
        P[((size_t)b * NXX + x) * NRR + r0 + lr] = __uint_as_float(f2tf32(e));
    }
    red[w][lr] = pt;
    __syncthreads();
    if (w == 0) {
        float s = red[0][lr];
#pragma unroll
        for (int i = 1; i < 8; i++) s += red[i][lr];
        psum[((size_t)b * 16 + xt) * NRR + r0 + lr] = s;
    }
}

// ---------------------------------------------------------------------------
// Kernel 3: rowsum[b,r] = sum over 16 x-blocks of psum (fixed order, determ.)
// ---------------------------------------------------------------------------
__global__ __launch_bounds__(256) void rowsum_reduce_kernel(
    const float* __restrict__ psum, float* __restrict__ rowsum)
{
    int idx = blockIdx.x * 256 + threadIdx.x;   // 0 .. BB*NRR-1
    int b = idx >> 9, r = idx & (NRR - 1);
    float s = 0.f;
#pragma unroll
    for (int t = 0; t < 16; t++)
        s += psum[((size_t)b * 16 + t) * NRR + r];
    rowsum[idx] = s;
}

// ---------------------------------------------------------------------------
// Kernel 4: out[b,r,e] = (sum_x P[b,x,r] * X[b,x,e]) / rowsum[b,r]
// cp.async 2-stage pipeline; P pre-rounded tf32, X raw (truncated) -> no cvt.
// ---------------------------------------------------------------------------
__global__ __launch_bounds__(256) void outgemm_kernel(
    const float* __restrict__ P, const float* __restrict__ X,
    const float* __restrict__ rowsum, float* __restrict__ out)
{
    __shared__ float Ps[2][32][72];
    __shared__ float Xs[2][32][72];

    const int tid  = threadIdx.x;
    const int lane = tid & 31;
    const int warp = tid >> 5;
    const int wm = warp >> 2;
    const int wn = warp & 3;
    const int r0 = blockIdx.x * 64;
    const int e0 = blockIdx.y * 64;
    const int b  = blockIdx.z;

    const int fr = lane >> 2;
    const int fc = lane & 3;

    const float* Pb = P + (size_t)b * NXX * NRR;
    const float* Xb = X + (size_t)b * NXX * DD;

    const int lrow = tid >> 3;
    const int lq   = (tid & 7) << 3;

    float c[2][2][4] = {};

    cp_async16(&Ps[0][lrow][lq    ], &Pb[(size_t)lrow * NRR + r0 + lq    ]);
    cp_async16(&Ps[0][lrow][lq + 4], &Pb[(size_t)lrow * NRR + r0 + lq + 4]);
    cp_async16(&Xs[0][lrow][lq    ], &Xb[(size_t)lrow * DD  + e0 + lq    ]);
    cp_async16(&Xs[0][lrow][lq + 4], &Xb[(size_t)lrow * DD  + e0 + lq + 4]);
    cp_commit();

    for (int i = 0; i < 16; i++) {
        const int cur = i & 1;
        cp_wait0();
        __syncthreads();

        if (i + 1 < 16) {
            const int nxt = cur ^ 1;
            const size_t krow = (size_t)((i + 1) * 32 + lrow);
            cp_async16(&Ps[nxt][lrow][lq    ], &Pb[krow * NRR + r0 + lq    ]);
            cp_async16(&Ps[nxt][lrow][lq + 4], &Pb[krow * NRR + r0 + lq + 4]);
            cp_async16(&Xs[nxt][lrow][lq    ], &Xb[krow * DD  + e0 + lq    ]);
            cp_async16(&Xs[nxt][lrow][lq + 4], &Xb[krow * DD  + e0 + lq + 4]);
            cp_commit();
        }

#pragma unroll
        for (int ks = 0; ks < 4; ks++) {
            const int k = ks << 3;
            unsigned a[2][4], bf[2][2];
#pragma unroll
            for (int mt = 0; mt < 2; mt++) {
                int mb = wm * 32 + mt * 16;
                a[mt][0] = __float_as_uint(Ps[cur][k + fc    ][mb + fr    ]);
                a[mt][1] = __float_as_uint(Ps[cur][k + fc    ][mb + fr + 8]);
                a[mt][2] = __float_as_uint(Ps[cur][k + fc + 4][mb + fr    ]);
                a[mt][3] = __float_as_uint(Ps[cur][k + fc + 4][mb + fr + 8]);
            }
#pragma unroll
            for (int nt = 0; nt < 2; nt++) {
                int nb = wn * 16 + nt * 8;
                bf[nt][0] = __float_as_uint(Xs[cur][k + fc    ][nb + fr]);
                bf[nt][1] = __float_as_uint(Xs[cur][k + fc + 4][nb + fr]);
            }
#pragma unroll
            for (int mt = 0; mt < 2; mt++)
#pragma unroll
                for (int nt = 0; nt < 2; nt++)
                    mma_tf32(c[mt][nt], a[mt], bf[nt]);
        }
    }

#pragma unroll
    for (int mt = 0; mt < 2; mt++) {
        int row0 = r0 + wm * 32 + mt * 16 + fr;
        float inv0 = 1.0f / rowsum[b * NRR + row0];
        float inv1 = 1.0f / rowsum[b * NRR + row0 + 8];
#pragma unroll
        for (int nt = 0; nt < 2; nt++) {
            int col = e0 + wn * 16 + nt * 8 + 2 * fc;
            float2 o0 = {c[mt][nt][0] * inv0, c[mt][nt][1] * inv0};
            float2 o1 = {c[mt][nt][2] * inv1, c[mt][nt][3] * inv1};
            *(float2*)&out[((size_t)b * NRR + row0) * DD + col]     = o0;
            *(float2*)&out[((size_t)b * NRR + row0 + 8) * DD + col] = o1;
        }
    }
}

// ---------------------------------------------------------------------------
extern "C" void kernel_launch(void* const* d_in, const int* in_sizes, int n_in,
                              void* d_out, int out_size)
{
    const float* X     = (const float*)d_in[0];
    const float* ref   = (const float*)d_in[1];
    const float* W_X   = (const float*)d_in[2];
    const float* b_X   = (const float*)d_in[3];
    const float* W_ref = (const float*)d_in[4];
    const float* b_ref = (const float*)d_in[5];
    const float* v_w   = (const float*)d_in[6];
    const float* v_b   = (const float*)d_in[7];
    float* out = (float*)d_out;

    float *hX, *hR, *P, *psum, *rowsum;
    cudaGetSymbolAddress((void**)&hX,     g_hX);
    cudaGetSymbolAddress((void**)&hR,     g_hR);
    cudaGetSymbolAddress((void**)&P,      g_P);
    cudaGetSymbolAddress((void**)&psum,   g_psum);
    cudaGetSymbolAddress((void**)&rowsum, g_rowsum);

    // Projections (tf32 MMA, raw-fp32 operands)
    proj_mma_kernel<<<dim3(BB * NXX / 128, HH / 64, 2), 256>>>(
        X, W_X, b_X, hX, ref, W_ref, b_ref, hR);

    // Scores fused with exp + P write + partial rowsums
    score_kernel<<<dim3(NXX / 32, NRR / 32, BB), 256>>>(hX, hR, v_w, v_b, P, psum);

    // Deterministic rowsum reduction
    rowsum_reduce_kernel<<<BB * NRR / 256, 256>>>(psum, rowsum);

    // Weighted sum + normalize (tf32 MMA, cp.async, no cvt)
    outgemm_kernel<<<dim3(NRR / 64, DD / 64, BB), 256>>>(P, X, rowsum, out);
}

// round 13
// speedup vs baseline: 1.1883x; 1.0297x over previous
#include <cuda_runtime.h>
#include <cuda_fp16.h>

// Problem constants (fixed by the dataset)
#define BB 8
#define NXX 512
#define NRR 512
#define DD 256
#define HH 256

// Score hybrid split (pipe-balanced): 128 h via MUFU tanh, 128 h via FFMA2
#define HMU 128
#define HM_PH 64     // MUFU h per phase (2 phases)
#define HP_PH 64     // poly h per phase (32 pairs)

// Scratch (no cudaMalloc allowed)
__device__ float g_hX[BB * NXX * HH];       // [b, x, h]
__device__ float g_hR[BB * NRR * HH];       // [b, r, h]
__device__ float g_P[BB * NXX * NRR];       // [b, x, r]  tf32(exp(S))
__device__ float g_psum[BB * 16 * NRR];     // [b, xblk, r] partial exp-sums
__device__ float g_rowsum[BB * NRR];        // [b, r]

// ---------------------------------------------------------------------------
// helpers
// ---------------------------------------------------------------------------
__device__ __forceinline__ unsigned f2tf32(float x) {
    unsigned r;
    asm("cvt.rna.tf32.f32 %0, %1;" : "=r"(r) : "f"(x));
    return r;
}
// RNA rounding to tf32 done on the ALU pipe: +half-ulp of the 13 dropped bits.
__device__ __forceinline__ unsigned rnd13(float x) {
    return __float_as_uint(x) + 0x1000u;
}
__device__ __forceinline__ float4 rnd4(float4 v) {
    v.x = __uint_as_float(rnd13(v.x));
    v.y = __uint_as_float(rnd13(v.y));
    v.z = __uint_as_float(rnd13(v.z));
    v.w = __uint_as_float(rnd13(v.w));
    return v;
}

__device__ __forceinline__ void mma_tf32(float* c, const unsigned* a, const unsigned* b) {
    asm volatile(
        "mma.sync.aligned.m16n8k8.row.col.f32.tf32.tf32.f32 "
        "{%0,%1,%2,%3}, {%4,%5,%6,%7}, {%8,%9}, {%0,%1,%2,%3};\n"
        : "+f"(c[0]), "+f"(c[1]), "+f"(c[2]), "+f"(c[3])
        : "r"(a[0]), "r"(a[1]), "r"(a[2]), "r"(a[3]), "r"(b[0]), "r"(b[1]));
}

__device__ __forceinline__ void cp_async16(void* smem, const void* gmem) {
    unsigned s = (unsigned)__cvta_generic_to_shared(smem);
    asm volatile("cp.async.cg.shared.global [%0], [%1], 16;" :: "r"(s), "l"(gmem));
}
__device__ __forceinline__ void cp_commit() {
    asm volatile("cp.async.commit_group;" ::: "memory");
}
template <int N>
__device__ __forceinline__ void cp_wait() {
    asm volatile("cp.async.wait_group %0;" :: "n"(N) : "memory");
}

// packed f32x2 (Blackwell dual-FP32)
__device__ __forceinline__ void fma2(unsigned long long& d, unsigned long long a,
                                     unsigned long long b, unsigned long long c) {
    asm("fma.rn.f32x2 %0, %1, %2, %3;" : "=l"(d) : "l"(a), "l"(b), "l"(c));
}
__device__ __forceinline__ void mul2(unsigned long long& d, unsigned long long a,
                                     unsigned long long b) {
    asm("mul.rn.f32x2 %0, %1, %2;" : "=l"(d) : "l"(a), "l"(b));
}
__device__ __forceinline__ unsigned long long add2_(unsigned long long a,
                                                    unsigned long long b) {
    unsigned long long d;
    asm("add.rn.f32x2 %0, %1, %2;" : "=l"(d) : "l"(a), "l"(b));
    return d;
}
__device__ __forceinline__ unsigned long long pk(float a, float b) {
    unsigned long long r;
    asm("mov.b64 %0, {%1,%2};" : "=l"(r) : "f"(a), "f"(b));
    return r;
}
__device__ __forceinline__ void upk(unsigned long long p, float& a, float& b) {
    asm("mov.b64 {%0,%1}, %2;" : "=f"(a), "=f"(b) : "l"(p));
}
__device__ __forceinline__ float tanhf_mufu(float t) {
    float th;
    asm("tanh.approx.f32 %0, %1;" : "=f"(th) : "f"(t));
    return th;
}

// ---------------------------------------------------------------------------
// Kernel 1: projection GEMM (tf32 MMA, double-buffered).
// Operands RNA-rounded to tf32 at smem store via ALU-pipe bit add (no XU).
// ---------------------------------------------------------------------------
__global__ __launch_bounds__(256) void proj_mma_kernel(
    const float* __restrict__ A0, const float* __restrict__ W0,
    const float* __restrict__ bias0, float* __restrict__ out0,
    const float* __restrict__ A1, const float* __restrict__ W1,
    const float* __restrict__ bias1, float* __restrict__ out1)
{
    const float* A    = blockIdx.z ? A1 : A0;
    const float* W    = blockIdx.z ? W1 : W0;
    const float* bias = blockIdx.z ? bias1 : bias0;
    float* out        = blockIdx.z ? out1 : out0;

    __shared__ float As[2][128][36];
    __shared__ float Ws[2][64][36];

    const int tid  = threadIdx.x;
    const int lane = tid & 31;
    const int warp = tid >> 5;
    const int wm = warp >> 1;
    const int wn = warp & 1;
    const int m0 = blockIdx.x * 128;
    const int n0 = blockIdx.y * 64;

    const int fr = lane >> 2;
    const int fc = lane & 3;

    const int ar = tid >> 1;
    const int aq = (tid & 1) << 4;
    const int wr = tid >> 2;
    const int wq = (tid & 3) << 3;

    float c[2][4][4] = {};

    {
        const float* Arow = &A[(size_t)(m0 + ar) * DD + aq];
        const float* Wrow = &W[(size_t)(n0 + wr) * DD + wq];
#pragma unroll
        for (int u = 0; u < 4; u++)
            *(float4*)&As[0][ar][aq + 4*u] = rnd4(*(const float4*)&Arow[4*u]);
#pragma unroll
        for (int u = 0; u < 2; u++)
            *(float4*)&Ws[0][wr][wq + 4*u] = rnd4(*(const float4*)&Wrow[4*u]);
    }
    __syncthreads();

    int cur = 0;
    for (int kc = 0; kc < DD; kc += 32) {
        const int nk = kc + 32;
        float4 pa[4], pw[2];
        if (nk < DD) {
            const float* Arow = &A[(size_t)(m0 + ar) * DD + nk + aq];
            const float* Wrow = &W[(size_t)(n0 + wr) * DD + nk + wq];
#pragma unroll
            for (int u = 0; u < 4; u++) pa[u] = *(const float4*)&Arow[4*u];
#pragma unroll
            for (int u = 0; u < 2; u++) pw[u] = *(const float4*)&Wrow[4*u];
        }

#pragma unroll
        for (int ks = 0; ks < 4; ks++) {
            const int k = ks << 3;
            unsigned a[2][4], b[4][2];
#pragma unroll
            for (int mt = 0; mt < 2; mt++) {
                int mb = wm * 32 + mt * 16;
                a[mt][0] = __float_as_uint(As[cur][mb + fr    ][k + fc    ]);
                a[mt][1] = __float_as_uint(As[cur][mb + fr + 8][k + fc    ]);
                a[mt][2] = __float_as_uint(As[cur][mb + fr    ][k + fc + 4]);
                a[mt][3] = __float_as_uint(As[cur][mb + fr + 8][k + fc + 4]);
            }
#pragma unroll
            for (int nt = 0; nt < 4; nt++) {
                int nb = wn * 32 + nt * 8;
                b[nt][0] = __float_as_uint(Ws[cur][nb + fr][k + fc    ]);
                b[nt][1] = __float_as_uint(Ws[cur][nb + fr][k + fc + 4]);
            }
#pragma unroll
            for (int mt = 0; mt < 2; mt++)
#pragma unroll
                for (int nt = 0; nt < 4; nt++)
                    mma_tf32(c[mt][nt], a[mt], b[nt]);
        }

        if (nk < DD) {
            const int nxt = cur ^ 1;
#pragma unroll
            for (int u = 0; u < 4; u++) *(float4*)&As[nxt][ar][aq + 4*u] = rnd4(pa[u]);
#pragma unroll
            for (int u = 0; u < 2; u++) *(float4*)&Ws[nxt][wr][wq + 4*u] = rnd4(pw[u]);
            __syncthreads();
            cur = nxt;
        }
    }

#pragma unroll
    for (int mt = 0; mt < 2; mt++) {
        int row0 = m0 + wm * 32 + mt * 16 + fr;
#pragma unroll
        for (int nt = 0; nt < 4; nt++) {
            int col = n0 + wn * 32 + nt * 8 + 2 * fc;
            float2 bv = *(const float2*)&bias[col];
            float2 o0 = {c[mt][nt][0] + bv.x, c[mt][nt][1] + bv.y};
            float2 o1 = {c[mt][nt][2] + bv.x, c[mt][nt][3] + bv.y};
            *(float2*)&out[(size_t)row0 * HH + col]       = o0;
            *(float2*)&out[(size_t)(row0 + 8) * HH + col] = o1;
        }
    }
}

// ---------------------------------------------------------------------------
// Score (fused exp + partial rowsum).  h < 128: MUFU tanh with float4 LDS +
// packed f32x2 add/fma (min issue overhead).  h >= 128: tanh(t)=1-2/(1+e^{2t}),
// reciprocal on FMA pipe (seed 0xFEF127EA-bits, 2 Newton, f32x2).
// Epilogue: P = tf32(exp(score)); per-block partial sums -> psum.
// ---------------------------------------------------------------------------
__device__ __forceinline__ void poly_pair(
    const float2 (&pXs2)[32][32], const float2 (&pRt2)[32][33],
    const float2* v2p, int q, int w4, int lr, unsigned long long accp[4])
{
    unsigned long long pR2 = *(const unsigned long long*)&pRt2[q][lr];
    unsigned long long vv2 = *(const unsigned long long*)&v2p[q];
#pragma unroll
    for (int j = 0; j < 4; j++) {
        unsigned long long pX2 = *(const unsigned long long*)&pXs2[w4 + j][q];
        unsigned long long d2, t2, g2;
        unsigned lo, hi;
        fma2(d2, pX2, pR2, 0x3F8000003F800000ULL);            // d = p + 1
        asm("mov.b64 {%0,%1}, %2;" : "=r"(lo), "=r"(hi) : "l"(d2));
        lo = 0xFEF127EAu - lo;                                 // -1/d seed
        hi = 0xFEF127EAu - hi;
        asm("mov.b64 %0, {%1,%2};" : "=l"(g2) : "r"(lo), "r"(hi));
        fma2(t2, d2, g2, 0x4000000040000000ULL);               // t = 2 - d*g
        mul2(g2, g2, t2);
        fma2(t2, d2, g2, 0x4000000040000000ULL);
        mul2(g2, g2, t2);                                      // gneg ~ -1/d
        fma2(accp[j], vv2, g2, accp[j]);                       // += 2v * gneg
    }
}

__global__ __launch_bounds__(256) void score_kernel(
    const float* __restrict__ hX, const float* __restrict__ hR,
    const float* __restrict__ vw, const float* __restrict__ vb,
    float* __restrict__ P, float* __restrict__ psum)
{
    __shared__ float  hXs[32][64];     // [x][h] MUFU range; broadcast float4
    __shared__ float  hRs[32][68];     // [r][h] MUFU range; per-lane float4 (pad 68)
    __shared__ float2 pXs2[32][32];    // e^{2hX} pairs, poly range; broadcast
    __shared__ float2 pRt2[32][33];    // e^{2hR} pairs transposed; per-lane
    __shared__ float  v_s[HH];
    __shared__ float2 v2s[64];         // (2v, 2v) poly range
    __shared__ float  red[8][32];

    const int xt = blockIdx.x, rt = blockIdx.y, b = blockIdx.z;
    const int x0 = xt * 32, r0 = rt * 32;
    const int tid = threadIdx.x;
    const int lr = tid & 31;
    const int w  = tid >> 5;
    const int w4 = w << 2;

    v_s[tid] = vw[tid];
    if (tid < 64) {
        float a = vw[HMU + 2 * tid], c = vw[HMU + 2 * tid + 1];
        v2s[tid] = make_float2(2.0f * a, 2.0f * c);
    }

    const float* hXb = hX + (size_t)(b * NXX + x0) * HH;
    const float* hRb = hR + (size_t)(b * NRR + r0) * HH;

    unsigned long long accm[4] = {0ULL, 0ULL, 0ULL, 0ULL};
    unsigned long long accp[4] = {0ULL, 0ULL, 0ULL, 0ULL};

    for (int ph = 0; ph < 2; ph++) {
        __syncthreads();
        // MUFU-range tiles: 32 rows x 16 float4 each (straight copies)
        for (int i = tid; i < 32 * 16; i += 256) {
            int row = i >> 4, q = (i & 15) << 2;
            *(float4*)&hXs[row][q] = *(const float4*)&hXb[row * HH + ph * HM_PH + q];
            *(float4*)&hRs[row][q] = *(const float4*)&hRb[row * HH + ph * HM_PH + q];
        }
        // poly-range tiles (exponentiate at load): 32 rows x 16 float4
        for (int i = tid; i < 32 * 16; i += 256) {
            int row = i >> 4, q = (i & 15) << 2;
            float4 vx = *(const float4*)&hXb[row * HH + HMU + ph * HP_PH + q];
            pXs2[row][(q >> 1)    ] = make_float2(__expf(2.f * vx.x), __expf(2.f * vx.y));
            pXs2[row][(q >> 1) + 1] = make_float2(__expf(2.f * vx.z), __expf(2.f * vx.w));
            float4 vr = *(const float4*)&hRb[row * HH + HMU + ph * HP_PH + q];
            pRt2[(q >> 1)    ][row] = make_float2(__expf(2.f * vr.x), __expf(2.f * vr.y));
            pRt2[(q >> 1) + 1][row] = make_float2(__expf(2.f * vr.z), __expf(2.f * vr.w));
        }
        __syncthreads();

        const float2* v2p = &v2s[ph * 32];

        for (int it = 0; it < 16; it++) {
            const int h = it << 2;
            float4 hr4 = *(const float4*)&hRs[lr][h];
            float4 v4  = *(const float4*)&v_s[ph * HM_PH + h];
            unsigned long long hr01 = pk(hr4.x, hr4.y);
            unsigned long long hr23 = pk(hr4.z, hr4.w);
            unsigned long long v01  = pk(v4.x, v4.y);
            unsigned long long v23  = pk(v4.z, v4.w);
#pragma unroll
            for (int j = 0; j < 4; j++) {
                float4 hx4 = *(const float4*)&hXs[w4 + j][h];
                unsigned long long t01 = add2_(pk(hx4.x, hx4.y), hr01);
                unsigned long long t23 = add2_(pk(hx4.z, hx4.w), hr23);
                float ta, tb, tc, td;
                upk(t01, ta, tb); upk(t23, tc, td);
                ta = tanhf_mufu(ta); tb = tanhf_mufu(tb);
                tc = tanhf_mufu(tc); td = tanhf_mufu(td);
                fma2(accm[j], pk(ta, tb), v01, accm[j]);
                fma2(accm[j], pk(tc, td), v23, accm[j]);
            }
            poly_pair(pXs2, pRt2, v2p, 2 * it,     w4, lr, accp);
            poly_pair(pXs2, pRt2, v2p, 2 * it + 1, w4, lr, accp);
        }
    }

    // constant term: vb + sum of v over poly range
    float C = vb[0];
#pragma unroll 8
    for (int h = HMU; h < HH; h++) C += v_s[h];

    // epilogue: exp, write tf32(exp), accumulate partial rowsum
    float pt = 0.f;
#pragma unroll
    for (int j = 0; j < 4; j++) {
        float m0, m1, p0, p1;
        upk(accm[j], m0, m1);
        upk(accp[j], p0, p1);
        float s = (m0 + m1) + (p0 + p1) + C;
        float e = __expf(s);
        pt += e;
        int x = x0 + w4 + j;
        P[((size_t)b * NXX + x) * NRR + r0 + lr] = __uint_as_float(f2tf32(e));
    }
    red[w][lr] = pt;
    __syncthreads();
    if (w == 0) {
        float s = red[0][lr];
#pragma unroll
        for (int i = 1; i < 8; i++) s += red[i][lr];
        psum[((size_t)b * 16 + xt) * NRR + r0 + lr] = s;
    }
}

// ---------------------------------------------------------------------------
// Kernel 3: rowsum[b,r] = sum over 16 x-blocks of psum (fixed order, determ.)
// ---------------------------------------------------------------------------
__global__ __launch_bounds__(256) void rowsum_reduce_kernel(
    const float* __restrict__ psum, float* __restrict__ rowsum)
{
    int idx = blockIdx.x * 256 + threadIdx.x;   // 0 .. BB*NRR-1
    int b = idx >> 9, r = idx & (NRR - 1);
    float s = 0.f;
#pragma unroll
    for (int t = 0; t < 16; t++)
        s += psum[((size_t)b * 16 + t) * NRR + r];
    rowsum[idx] = s;
}

// ---------------------------------------------------------------------------
// Kernel 4: out[b,r,e] = (sum_x P[b,x,r] * X[b,x,e]) / rowsum[b,r]
// 3-stage cp.async pipeline (wait_group 1 hides a full chunk's latency).
// P pre-rounded tf32; X RNA-rounded at fragment load (ALU-pipe bit add).
// ---------------------------------------------------------------------------
__global__ __launch_bounds__(256) void outgemm_kernel(
    const float* __restrict__ P, const float* __restrict__ X,
    const float* __restrict__ rowsum, float* __restrict__ out)
{
    __shared__ float Ps[3][32][72];
    __shared__ float Xs[3][32][72];

    const int tid  = threadIdx.x;
    const int lane = tid & 31;
    const int warp = tid >> 5;
    const int wm = warp >> 2;
    const int wn = warp & 3;
    const int r0 = blockIdx.x * 64;
    const int e0 = blockIdx.y * 64;
    const int b  = blockIdx.z;

    const int fr = lane >> 2;
    const int fc = lane & 3;

    const float* Pb = P + (size_t)b * NXX * NRR;
    const float* Xb = X + (size_t)b * NXX * DD;

    const int lrow = tid >> 3;
    const int lq   = (tid & 7) << 3;

    float c[2][2][4] = {};

    // prologue: chunks 0 and 1
#pragma unroll
    for (int pc = 0; pc < 2; pc++) {
        const size_t krow = (size_t)(pc * 32 + lrow);
        cp_async16(&Ps[pc][lrow][lq    ], &Pb[krow * NRR + r0 + lq    ]);
        cp_async16(&Ps[pc][lrow][lq + 4], &Pb[krow * NRR + r0 + lq + 4]);
        cp_async16(&Xs[pc][lrow][lq    ], &Xb[krow * DD  + e0 + lq    ]);
        cp_async16(&Xs[pc][lrow][lq + 4], &Xb[krow * DD  + e0 + lq + 4]);
        cp_commit();
    }

    for (int i = 0; i < 16; i++) {
        const int cur = i % 3;
        if (i < 14) cp_wait<1>(); else cp_wait<0>();
        __syncthreads();

        if (i + 2 < 16) {
            const int nxt = (i + 2) % 3;
            const size_t krow = (size_t)((i + 2) * 32 + lrow);
            cp_async16(&Ps[nxt][lrow][lq    ], &Pb[krow * NRR + r0 + lq    ]);
            cp_async16(&Ps[nxt][lrow][lq + 4], &Pb[krow * NRR + r0 + lq + 4]);
            cp_async16(&Xs[nxt][lrow][lq    ], &Xb[krow * DD  + e0 + lq    ]);
            cp_async16(&Xs[nxt][lrow][lq + 4], &Xb[krow * DD  + e0 + lq + 4]);
            cp_commit();
        }

#pragma unroll
        for (int ks = 0; ks < 4; ks++) {
            const int k = ks << 3;
            unsigned a[2][4], bf[2][2];
#pragma unroll
            for (int mt = 0; mt < 2; mt++) {
                int mb = wm * 32 + mt * 16;
                a[mt][0] = __float_as_uint(Ps[cur][k + fc    ][mb + fr    ]);
                a[mt][1] = __float_as_uint(Ps[cur][k + fc    ][mb + fr + 8]);
                a[mt][2] = __float_as_uint(Ps[cur][k + fc + 4][mb + fr    ]);
                a[mt][3] = __float_as_uint(Ps[cur][k + fc + 4][mb + fr + 8]);
            }
#pragma unroll
            for (int nt = 0; nt < 2; nt++) {
                int nb = wn * 16 + nt * 8;
                bf[nt][0] = rnd13(Xs[cur][k + fc    ][nb + fr]);
                bf[nt][1] = rnd13(Xs[cur][k + fc + 4][nb + fr]);
            }
#pragma unroll
            for (int mt = 0; mt < 2; mt++)
#pragma unroll
                for (int nt = 0; nt < 2; nt++)
                    mma_tf32(c[mt][nt], a[mt], bf[nt]);
        }
    }

#pragma unroll
    for (int mt = 0; mt < 2; mt++) {
        int row0 = r0 + wm * 32 + mt * 16 + fr;
        float inv0 = 1.0f / rowsum[b * NRR + row0];
        float inv1 = 1.0f / rowsum[b * NRR + row0 + 8];
#pragma unroll
        for (int nt = 0; nt < 2; nt++) {
            int col = e0 + wn * 16 + nt * 8 + 2 * fc;
            float2 o0 = {c[mt][nt][0] * inv0, c[mt][nt][1] * inv0};
            float2 o1 = {c[mt][nt][2] * inv1, c[mt][nt][3] * inv1};
            *(float2*)&out[((size_t)b * NRR + row0) * DD + col]     = o0;
            *(float2*)&out[((size_t)b * NRR + row0 + 8) * DD + col] = o1;
        }
    }
}

// ---------------------------------------------------------------------------
extern "C" void kernel_launch(void* const* d_in, const int* in_sizes, int n_in,
                              void* d_out, int out_size)
{
    const float* X     = (const float*)d_in[0];
    const float* ref   = (const float*)d_in[1];
    const float* W_X   = (const float*)d_in[2];
    const float* b_X   = (const float*)d_in[3];
    const float* W_ref = (const float*)d_in[4];
    const float* b_ref = (const float*)d_in[5];
    const float* v_w   = (const float*)d_in[6];
    const float* v_b   = (const float*)d_in[7];
    float* out = (float*)d_out;

    float *hX, *hR, *P, *psum, *rowsum;
    cudaGetSymbolAddress((void**)&hX,     g_hX);
    cudaGetSymbolAddress((void**)&hR,     g_hR);
    cudaGetSymbolAddress((void**)&P,      g_P);
    cudaGetSymbolAddress((void**)&psum,   g_psum);
    cudaGetSymbolAddress((void**)&rowsum, g_rowsum);

    // Projections (tf32 MMA, RNA-rounded operands)
    proj_mma_kernel<<<dim3(BB * NXX / 128, HH / 64, 2), 256>>>(
        X, W_X, b_X, hX, ref, W_ref, b_ref, hR);

    // Scores fused with exp + P write + partial rowsums
    score_kernel<<<dim3(NXX / 32, NRR / 32, BB), 256>>>(hX, hR, v_w, v_b, P, psum);

    // Deterministic rowsum reduction
    rowsum_reduce_kernel<<<BB * NRR / 256, 256>>>(psum, rowsum);

    // Weighted sum + normalize (tf32 MMA, 3-stage cp.async)
    outgemm_kernel<<<dim3(NRR / 64, DD / 64, BB), 256>>>(P, X, rowsum, out);
}